// round 11
// baseline (speedup 1.0000x reference)
#include <cuda_runtime.h>
#include <stdint.h>

// GreedyGroupedRouter: SEQ=524288 tokens, 256 experts, 8 groups of 32, top-1/group.
// d_out layout (float32): rw[SEQ*256] | tw[SEQ*8] | tids[SEQ*8] | hist[256]
//
// R1/R10 champion router body (unchanged memory shape), grid = 1216 (152 SMs
// x 8 blocks, one full wave), single graph node. Changes this round:
//  - per-row histogram atomics collapsed from 8 predicated single-lane ATOMS
//    to one 8-lane spread ATOMS after the gather
//  - hist finalization via u32 device accumulator drained (and re-zeroed) by
//    the last block with atomicExch -> no init flag, no spin, replay-safe.

#define SEQ     524288
#define NE      256
#define NG      8
#define GS      32
#define TOPK    8

__device__ unsigned g_hist_u32[NE];     // zero-initialized; drained each replay
__device__ unsigned g_done_blocks = 0;

__global__ void __launch_bounds__(256)
router_kernel(const float* __restrict__ logits,
              float* __restrict__ rw,     // [SEQ, 256]
              float* __restrict__ tw,     // [SEQ, 8]
              float* __restrict__ tids,   // [SEQ, 8]
              float* __restrict__ hist)   // [256]
{
    __shared__ unsigned int shist[NE];
    for (int i = threadIdx.x; i < NE; i += blockDim.x) shist[i] = 0u;
    __syncthreads();

    const int lane   = threadIdx.x & 31;
    const int gwarp  = blockIdx.x * (blockDim.x >> 5) + (threadIdx.x >> 5);
    const int nwarps = gridDim.x * (blockDim.x >> 5);

    for (int row = gwarp; row < SEQ; row += nwarps) {
        const float* lp = logits + (size_t)row * NE;

        // Lane-strided: lane holds element (lane + 32*i); register i is this
        // lane's member of expert-group i. Each load is a coalesced 128B.
        float x[NG];
        #pragma unroll
        for (int i = 0; i < NG; i++) x[i] = lp[lane + GS * i];

        // Row max (softmax stabilization)
        float m = x[0];
        #pragma unroll
        for (int i = 1; i < NG; i++) m = fmaxf(m, x[i]);
        #pragma unroll
        for (int o = 16; o > 0; o >>= 1)
            m = fmaxf(m, __shfl_xor_sync(0xffffffffu, m, o));

        // exp + row sum
        float e[NG];
        float s = 0.0f;
        #pragma unroll
        for (int i = 0; i < NG; i++) { e[i] = __expf(x[i] - m); s += e[i]; }
        #pragma unroll
        for (int o = 16; o > 0; o >>= 1)
            s += __shfl_xor_sync(0xffffffffu, s, o);
        const float inv = 1.0f / s;

        // Softmax weights + immediate streaming store of routing_weights
        float* rp = rw + (size_t)row * NE;
        float w[NG];
        #pragma unroll
        for (int i = 0; i < NG; i++) {
            w[i] = e[i] * inv;
            rp[lane + GS * i] = w[i];
        }

        // Per-group argmax (group g = lanes' w[g]); tie-break to lowest index,
        // matching lax.top_k. Softmax values in (0,1] -> float bits monotone.
        float myw  = 0.0f;   // valid on lanes 0..7
        int   myid = 0;
        float sw   = 0.0f;
        #pragma unroll
        for (int g = 0; g < NG; g++) {
            unsigned u    = __float_as_uint(w[g]);
            unsigned umax = __reduce_max_sync(0xffffffffu, u);
            unsigned bal  = __ballot_sync(0xffffffffu, u == umax);
            int src       = __ffs(bal) - 1;           // lowest winning lane
            float gv      = __uint_as_float(umax);
            sw += gv;
            if (lane == g) { myw = gv; myid = g * GS + src; }
        }
        const float invsw = 1.0f / (sw + 1e-20f);

        if (lane < TOPK) {
            tw[(size_t)row * TOPK + lane]   = myw * invsw;
            tids[(size_t)row * TOPK + lane] = (float)myid;
            atomicAdd(&shist[myid], 1u);   // one spread-address ATOMS per row
        }
    }

    __syncthreads();

    // Per-block flush into the u32 device accumulator.
    for (int i = threadIdx.x; i < NE; i += blockDim.x) {
        unsigned c = shist[i];
        if (c) atomicAdd(&g_hist_u32[i], c);
    }

    __syncthreads();
    __shared__ unsigned s_last;
    if (threadIdx.x == 0) {
        __threadfence();
        s_last = (atomicAdd(&g_done_blocks, 1u) == gridDim.x - 1) ? 1u : 0u;
    }
    __syncthreads();

    // Last block drains the accumulator to the float output, simultaneously
    // re-zeroing it for the next graph replay. Counter reset likewise.
    if (s_last) {
        __threadfence();                           // acquire all blocks' adds
        for (int i = threadIdx.x; i < NE; i += blockDim.x) {
            unsigned v = atomicExch(&g_hist_u32[i], 0u);
            hist[i] = (float)v;
        }
        if (threadIdx.x == 0) atomicExch(&g_done_blocks, 0u);
    }
}

extern "C" void kernel_launch(void* const* d_in, const int* in_sizes, int n_in,
                              void* d_out, int out_size) {
    const float* logits = (const float*)d_in[0];
    float* out  = (float*)d_out;
    float* rw   = out;
    float* tw   = rw   + (size_t)SEQ * NE;
    float* tids = tw   + (size_t)SEQ * TOPK;
    float* hist = tids + (size_t)SEQ * TOPK;

    // One full wave on GB300: 152 SMs x 8 blocks = 1216 (64 warps/SM).
    router_kernel<<<1216, 256>>>(logits, rw, tw, tids, hist);
}